// round 5
// baseline (speedup 1.0000x reference)
#include <cuda_runtime.h>
#include <cuda_bf16.h>
#include <math.h>

#define N_NODES 100000
#define N_EDGES 600000
#define HID 128
#define SCAN_BLOCKS ((N_NODES + 255) / 256)   // 391
#define XPAD 132                               // padded row length (floats)

typedef unsigned int uint;

// ---------------- device scratch (no allocs allowed) ----------------
__device__ float g_H[(size_t)N_NODES * HID];
__device__ float g_A[(size_t)N_NODES * HID];
__device__ float g_dinv[N_NODES];
__device__ float g_recip[N_NODES];
__device__ int   g_cnt[N_NODES];
__device__ int   g_fill[N_NODES];
__device__ int   g_rowptr[N_NODES + 1];
__device__ int   g_bsum[512];
__device__ int   g_csr_src[N_EDGES];
__device__ float g_gate[HID];
__device__ int   g_is64;
__device__ uint  g_Wh[3][8192];
__device__ uint  g_Wl[3][8192];

__device__ __forceinline__ int edge_src(const int* ei, int e, int is64) {
    return is64 ? ei[2 * e] : ei[e];
}
__device__ __forceinline__ int edge_dst(const int* ei, int e, int is64) {
    return is64 ? ei[2 * (N_EDGES + e)] : ei[N_EDGES + e];
}

// ---------------- K0: zero counts + dtype detect ----------------
__global__ void init_kernel(const int* __restrict__ ei) {
    int i = blockIdx.x * blockDim.x + threadIdx.x;
    if (i < N_NODES) g_cnt[i] = 0;
    if (blockIdx.x == 0) {
        __shared__ int any_nz;
        if (threadIdx.x == 0) any_nz = 0;
        __syncthreads();
        int local = 0;
        for (int j = threadIdx.x; j < 4096; j += 256) local |= ei[2 * j + 1];
        if (local) atomicOr(&any_nz, 1);
        __syncthreads();
        if (threadIdx.x == 0) g_is64 = (any_nz == 0) ? 1 : 0;
    }
}

// ---------------- K1: count in-degrees ----------------
__global__ void count_kernel(const int* __restrict__ ei) {
    int e = blockIdx.x * blockDim.x + threadIdx.x;
    if (e >= N_EDGES) return;
    atomicAdd(&g_cnt[edge_dst(ei, e, g_is64)], 1);
}

// ---------------- K2: block sums + degree normalizers ----------------
__global__ void scan1_deg_kernel() {
    __shared__ int sh[256];
    int i = blockIdx.x * 256 + threadIdx.x;
    int c = (i < N_NODES) ? g_cnt[i] : 0;
    if (i < N_NODES) {
        float deg = (float)c + 1.0f;
        g_dinv[i]  = rsqrtf(deg);
        g_recip[i] = 1.0f / deg;
    }
    sh[threadIdx.x] = c;
    __syncthreads();
#pragma unroll
    for (int s = 128; s > 0; s >>= 1) {
        if (threadIdx.x < s) sh[threadIdx.x] += sh[threadIdx.x + s];
        __syncthreads();
    }
    if (threadIdx.x == 0) g_bsum[blockIdx.x] = sh[0];
}

// ---------------- K3: exclusive scan of block sums ----------------
__global__ void scan2_kernel() {
    __shared__ int sh[512];
    int t = threadIdx.x;
    int v = (t < SCAN_BLOCKS) ? g_bsum[t] : 0;
    sh[t] = v;
    __syncthreads();
#pragma unroll
    for (int off = 1; off < 512; off <<= 1) {
        int x = (t >= off) ? sh[t - off] : 0;
        __syncthreads();
        sh[t] += x;
        __syncthreads();
    }
    if (t < SCAN_BLOCKS) g_bsum[t] = sh[t] - v;
}

// ---------------- K4: rowptr + fill cursors ----------------
__global__ void scan3_kernel() {
    __shared__ int sh[256];
    int i = blockIdx.x * 256 + threadIdx.x;
    int v = (i < N_NODES) ? g_cnt[i] : 0;
    sh[threadIdx.x] = v;
    __syncthreads();
#pragma unroll
    for (int off = 1; off < 256; off <<= 1) {
        int x = (threadIdx.x >= off) ? sh[threadIdx.x - off] : 0;
        __syncthreads();
        sh[threadIdx.x] += x;
        __syncthreads();
    }
    if (i < N_NODES) {
        g_rowptr[i] = g_bsum[blockIdx.x] + sh[threadIdx.x] - v;
        g_fill[i] = 0;
    }
    if (i == N_NODES - 1) g_rowptr[N_NODES] = N_EDGES;
}

// ---------------- K5: CSR fill ----------------
__global__ void fill_kernel(const int* __restrict__ ei) {
    int e = blockIdx.x * blockDim.x + threadIdx.x;
    if (e >= N_EDGES) return;
    int is64 = g_is64;
    int s = edge_src(ei, e, is64);
    int d = edge_dst(ei, e, is64);
    int pos = g_rowptr[d] + atomicAdd(&g_fill[d], 1);
    g_csr_src[pos] = s;
}

// ---------------- K6: gate MLP + W -> fragment-packed bf16 hi/lo (3 layers) ----------------
__global__ void gateconv_kernel(const float* __restrict__ t,
                                const float* __restrict__ Wg1, const float* __restrict__ bg1,
                                const float* __restrict__ Wg2, const float* __restrict__ bg2,
                                const float* __restrict__ W0, const float* __restrict__ W1,
                                const float* __restrict__ W2) {
    if (blockIdx.x == 96) {
        __shared__ float h1[HID];
        int j = threadIdx.x;
        if (j < HID) {
            float tv = t[0];
            h1[j] = tanhf(tv * Wg1[j] + bg1[j]);
        }
        __syncthreads();
        if (j < HID) {
            float s = bg2[j];
#pragma unroll 8
            for (int k = 0; k < HID; k++) s += h1[k] * Wg2[k * HID + j];
            g_gate[j] = 1.0f / (1.0f + expf(-s));
        }
        return;
    }
    int layer = blockIdx.x >> 5;
    const float* W = (layer == 0) ? W0 : ((layer == 1) ? W1 : W2);
    uint* Wh = g_Wh[layer];
    uint* Wl = g_Wl[layer];
    int tt = (blockIdx.x & 31) * 256 + threadIdx.x;
    int r = tt & 1, lane = (tt >> 1) & 31, nt = (tt >> 6) & 15, kc = tt >> 10;
    int k = kc * 16 + r * 8 + (lane & 3) * 2;
    int n = nt * 8 + (lane >> 2);
    float w0 = W[k * HID + n];
    float w1 = W[(k + 1) * HID + n];
    __nv_bfloat162 h = __floats2bfloat162_rn(w0, w1);
    __nv_bfloat162 l = __floats2bfloat162_rn(w0 - __bfloat162float(h.x),
                                             w1 - __bfloat162float(h.y));
    Wh[tt] = *(uint*)&h;
    Wl[tt] = *(uint*)&l;
}

// ---------------- MMA helpers ----------------
__device__ __forceinline__ void mma_bf16(float* c, const uint* a, const uint* b) {
    asm volatile(
        "mma.sync.aligned.m16n8k16.row.col.f32.bf16.bf16.f32 "
        "{%0,%1,%2,%3}, {%4,%5,%6,%7}, {%8,%9}, {%0,%1,%2,%3};"
        : "+f"(c[0]), "+f"(c[1]), "+f"(c[2]), "+f"(c[3])
        : "r"(a[0]), "r"(a[1]), "r"(a[2]), "r"(a[3]), "r"(b[0]), "r"(b[1]));
}

__device__ __forceinline__ void cvt_hilo(uint& hi, uint& lo, float2 v) {
    __nv_bfloat162 h = __floats2bfloat162_rn(v.x, v.y);
    __nv_bfloat162 l = __floats2bfloat162_rn(v.x - __bfloat162float(h.x),
                                             v.y - __bfloat162float(h.y));
    hi = *(uint*)&h;
    lo = *(uint*)&l;
}

// ---------------- layer-0 GEMM: H = X @ W0 (128-row tiles) ----------------
__global__ __launch_bounds__(256) void gemm_mma_kernel(
    const float* __restrict__ Xin, const uint* __restrict__ Wh,
    const uint* __restrict__ Wl, float* __restrict__ H) {
    extern __shared__ uint smem[];
    uint* sWh = smem;
    uint* sWl = smem + 8192;

    int tx = threadIdx.x;
#pragma unroll
    for (int i = tx; i < 2048; i += 256) {
        ((uint4*)sWh)[i] = ((const uint4*)Wh)[i];
        ((uint4*)sWl)[i] = ((const uint4*)Wl)[i];
    }
    __syncthreads();

    int warp = tx >> 5, lane = tx & 31;
    int gid = lane >> 2, tig = lane & 3;
    int rg  = blockIdx.x * 128 + warp * 16 + gid;
    int rg8 = rg + 8;
    bool v0 = rg < N_NODES, v8 = rg8 < N_NODES;
    const float* X0 = Xin + (size_t)rg  * HID;
    const float* X8 = Xin + (size_t)rg8 * HID;

    float c[16][4];
#pragma unroll
    for (int nt = 0; nt < 16; nt++)
#pragma unroll
        for (int r = 0; r < 4; r++) c[nt][r] = 0.f;

#pragma unroll
    for (int kc = 0; kc < 8; kc++) {
        int k0 = kc * 16 + tig * 2;
        uint ah[4], al[4];
        cvt_hilo(ah[0], al[0], v0 ? *(const float2*)(X0 + k0)     : make_float2(0.f, 0.f));
        cvt_hilo(ah[1], al[1], v8 ? *(const float2*)(X8 + k0)     : make_float2(0.f, 0.f));
        cvt_hilo(ah[2], al[2], v0 ? *(const float2*)(X0 + k0 + 8) : make_float2(0.f, 0.f));
        cvt_hilo(ah[3], al[3], v8 ? *(const float2*)(X8 + k0 + 8) : make_float2(0.f, 0.f));

        const uint* wh = sWh + (kc * 16) * 64 + lane * 2;
        const uint* wl = sWl + (kc * 16) * 64 + lane * 2;
#pragma unroll
        for (int nt = 0; nt < 16; nt++) {
            uint bh[2], bl[2];
            uint2 t0 = *(const uint2*)(wh + nt * 64);
            uint2 t1 = *(const uint2*)(wl + nt * 64);
            bh[0] = t0.x; bh[1] = t0.y;
            bl[0] = t1.x; bl[1] = t1.y;
            mma_bf16(c[nt], ah, bh);
            mma_bf16(c[nt], ah, bl);
            mma_bf16(c[nt], al, bh);
        }
    }

#pragma unroll
    for (int nt = 0; nt < 16; nt++) {
        int col = nt * 8 + tig * 2;
        if (v0) *(float2*)(H + (size_t)rg  * HID + col) = make_float2(c[nt][0], c[nt][1]);
        if (v8) *(float2*)(H + (size_t)rg8 * HID + col) = make_float2(c[nt][2], c[nt][3]);
    }
}

// ---------------- fused: gather(Hin)+bias -> relu*gate -> GEMM(W) -> Hout ----------------
// 512 threads = 16 warps; 256-node tile; warp w gathers nodes w*16..w*16+15 (its own MMA rows),
// stages activated rows in smem (XPAD-padded), then MMA.
__global__ __launch_bounds__(512) void fused_gg_kernel(
    const float* __restrict__ Hin, const uint* __restrict__ Wh,
    const uint* __restrict__ Wl, const float* __restrict__ b,
    float* __restrict__ Hout) {
    extern __shared__ uint smem[];
    uint* sWh = smem;                      // 32KB
    uint* sWl = smem + 8192;               // 32KB
    float* Xs = (float*)(smem + 16384);    // 256*XPAD floats = 132KB

    int tx = threadIdx.x;
#pragma unroll
    for (int i = tx; i < 2048; i += 512) {
        ((uint4*)sWh)[i] = ((const uint4*)Wh)[i];
        ((uint4*)sWl)[i] = ((const uint4*)Wl)[i];
    }

    int warp = tx >> 5, lane = tx & 31;

    // ---- gather phase ----
    float4 gv = ((const float4*)g_gate)[lane];
    float4 bv = ((const float4*)b)[lane];
    int nodebase = blockIdx.x * 256 + warp * 16;
#pragma unroll 1
    for (int i = 0; i < 16; i++) {
        int d = nodebase + i;
        float* xrow = Xs + (warp * 16 + i) * XPAD;
        if (d < N_NODES) {
            int beg = g_rowptr[d];
            int end = g_rowptr[d + 1];
            float ddinv = g_dinv[d];
            float rc = g_recip[d];
            float4 hv = ((const float4*)(Hin + (size_t)d * HID))[lane];
            float4 acc0 = make_float4(hv.x * rc, hv.y * rc, hv.z * rc, hv.w * rc);
            float4 acc1 = make_float4(0.f, 0.f, 0.f, 0.f);
            int e = beg;
            for (; e + 1 < end; e += 2) {
                int s0 = g_csr_src[e];
                int s1 = g_csr_src[e + 1];
                float w0 = ddinv * g_dinv[s0];
                float w1 = ddinv * g_dinv[s1];
                float4 h0 = ((const float4*)(Hin + (size_t)s0 * HID))[lane];
                float4 h1 = ((const float4*)(Hin + (size_t)s1 * HID))[lane];
                acc0.x += h0.x * w0; acc0.y += h0.y * w0; acc0.z += h0.z * w0; acc0.w += h0.w * w0;
                acc1.x += h1.x * w1; acc1.y += h1.y * w1; acc1.z += h1.z * w1; acc1.w += h1.w * w1;
            }
            if (e < end) {
                int s0 = g_csr_src[e];
                float w0 = ddinv * g_dinv[s0];
                float4 h0 = ((const float4*)(Hin + (size_t)s0 * HID))[lane];
                acc0.x += h0.x * w0; acc0.y += h0.y * w0; acc0.z += h0.z * w0; acc0.w += h0.w * w0;
            }
            float4 o;
            o.x = fmaxf(acc0.x + acc1.x + bv.x, 0.f) * gv.x;
            o.y = fmaxf(acc0.y + acc1.y + bv.y, 0.f) * gv.y;
            o.z = fmaxf(acc0.z + acc1.z + bv.z, 0.f) * gv.z;
            o.w = fmaxf(acc0.w + acc1.w + bv.w, 0.f) * gv.w;
            *(float4*)(xrow + lane * 4) = o;
        } else {
            *(float4*)(xrow + lane * 4) = make_float4(0.f, 0.f, 0.f, 0.f);
        }
    }
    __syncthreads();

    // ---- MMA phase ----
    int gid = lane >> 2, tig = lane & 3;
    int rl0 = warp * 16 + gid;
    const float* X0 = Xs + rl0 * XPAD;
    const float* X8 = X0 + 8 * XPAD;

    float c[16][4];
#pragma unroll
    for (int nt = 0; nt < 16; nt++)
#pragma unroll
        for (int r = 0; r < 4; r++) c[nt][r] = 0.f;

#pragma unroll
    for (int kc = 0; kc < 8; kc++) {
        int k0 = kc * 16 + tig * 2;
        uint ah[4], al[4];
        cvt_hilo(ah[0], al[0], *(const float2*)(X0 + k0));
        cvt_hilo(ah[1], al[1], *(const float2*)(X8 + k0));
        cvt_hilo(ah[2], al[2], *(const float2*)(X0 + k0 + 8));
        cvt_hilo(ah[3], al[3], *(const float2*)(X8 + k0 + 8));

        const uint* wh = sWh + (kc * 16) * 64 + lane * 2;
        const uint* wl = sWl + (kc * 16) * 64 + lane * 2;
#pragma unroll
        for (int nt = 0; nt < 16; nt++) {
            uint bh[2], bl[2];
            uint2 t0 = *(const uint2*)(wh + nt * 64);
            uint2 t1 = *(const uint2*)(wl + nt * 64);
            bh[0] = t0.x; bh[1] = t0.y;
            bl[0] = t1.x; bl[1] = t1.y;
            mma_bf16(c[nt], ah, bh);
            mma_bf16(c[nt], ah, bl);
            mma_bf16(c[nt], al, bh);
        }
    }

    int rg  = blockIdx.x * 256 + rl0;
    int rg8 = rg + 8;
    bool v0 = rg < N_NODES, v8 = rg8 < N_NODES;
#pragma unroll
    for (int nt = 0; nt < 16; nt++) {
        int col = nt * 8 + tig * 2;
        if (v0) *(float2*)(Hout + (size_t)rg  * HID + col) = make_float2(c[nt][0], c[nt][1]);
        if (v8) *(float2*)(Hout + (size_t)rg8 * HID + col) = make_float2(c[nt][2], c[nt][3]);
    }
}

// ---------------- final gather: out = relu(gather(Hin)+b) * gate ----------------
__global__ __launch_bounds__(256) void gather_final_kernel(const float* __restrict__ H,
                                                           const float* __restrict__ b,
                                                           float* __restrict__ out) {
    int gtid = blockIdx.x * blockDim.x + threadIdx.x;
    int d = gtid >> 5;
    int lane = threadIdx.x & 31;
    if (d >= N_NODES) return;

    int beg = g_rowptr[d];
    int end = g_rowptr[d + 1];
    float ddinv = g_dinv[d];
    float rc = g_recip[d];
    float4 hv = ((const float4*)(H + (size_t)d * HID))[lane];
    float4 acc0 = make_float4(hv.x * rc, hv.y * rc, hv.z * rc, hv.w * rc);
    float4 acc1 = make_float4(0.f, 0.f, 0.f, 0.f);

    int e = beg;
    for (; e + 1 < end; e += 2) {
        int s0 = g_csr_src[e];
        int s1 = g_csr_src[e + 1];
        float w0 = ddinv * g_dinv[s0];
        float w1 = ddinv * g_dinv[s1];
        float4 h0 = ((const float4*)(H + (size_t)s0 * HID))[lane];
        float4 h1 = ((const float4*)(H + (size_t)s1 * HID))[lane];
        acc0.x += h0.x * w0; acc0.y += h0.y * w0; acc0.z += h0.z * w0; acc0.w += h0.w * w0;
        acc1.x += h1.x * w1; acc1.y += h1.y * w1; acc1.z += h1.z * w1; acc1.w += h1.w * w1;
    }
    if (e < end) {
        int s0 = g_csr_src[e];
        float w0 = ddinv * g_dinv[s0];
        float4 h0 = ((const float4*)(H + (size_t)s0 * HID))[lane];
        acc0.x += h0.x * w0; acc0.y += h0.y * w0; acc0.z += h0.z * w0; acc0.w += h0.w * w0;
    }

    float4 bv = ((const float4*)b)[lane];
    float4 g = ((const float4*)g_gate)[lane];
    float4 o;
    o.x = fmaxf(acc0.x + acc1.x + bv.x, 0.f) * g.x;
    o.y = fmaxf(acc0.y + acc1.y + bv.y, 0.f) * g.y;
    o.z = fmaxf(acc0.z + acc1.z + bv.z, 0.f) * g.z;
    o.w = fmaxf(acc0.w + acc1.w + bv.w, 0.f) * g.w;
    ((float4*)(out + (size_t)d * HID))[lane] = o;
}

// ---------------- launch ----------------
extern "C" void kernel_launch(void* const* d_in, const int* in_sizes, int n_in,
                              void* d_out, int out_size) {
    const float* x   = (const float*)d_in[0];
    const int*   ei  = (const int*)d_in[1];
    const float* ts  = (const float*)d_in[2];
    const float* W0  = (const float*)d_in[3];
    const float* b0  = (const float*)d_in[4];
    const float* W1  = (const float*)d_in[5];
    const float* b1  = (const float*)d_in[6];
    const float* W2  = (const float*)d_in[7];
    const float* b2  = (const float*)d_in[8];
    const float* Wg1 = (const float*)d_in[9];
    const float* bg1 = (const float*)d_in[10];
    const float* Wg2 = (const float*)d_in[11];
    const float* bg2 = (const float*)d_in[12];
    float* out = (float*)d_out;

    const int SMEM_G = 16384 * 4;                        // 64KB (W hi/lo)
    const int SMEM_F = 16384 * 4 + 256 * XPAD * 4;       // 64KB + 132KB = 200704B
    cudaFuncSetAttribute(gemm_mma_kernel, cudaFuncAttributeMaxDynamicSharedMemorySize, SMEM_G);
    cudaFuncSetAttribute(fused_gg_kernel, cudaFuncAttributeMaxDynamicSharedMemorySize, SMEM_F);

    float *H, *A;
    uint *Wh, *Wl;
    cudaGetSymbolAddress((void**)&H,  g_H);
    cudaGetSymbolAddress((void**)&A,  g_A);
    cudaGetSymbolAddress((void**)&Wh, g_Wh);
    cudaGetSymbolAddress((void**)&Wl, g_Wl);

    const int eblk = (N_EDGES + 255) / 256;

    // prep (7 launches)
    init_kernel<<<SCAN_BLOCKS, 256>>>(ei);
    count_kernel<<<eblk, 256>>>(ei);
    scan1_deg_kernel<<<SCAN_BLOCKS, 256>>>();
    scan2_kernel<<<1, 512>>>();
    scan3_kernel<<<SCAN_BLOCKS, 256>>>();
    fill_kernel<<<eblk, 256>>>(ei);
    gateconv_kernel<<<97, 256>>>(ts, Wg1, bg1, Wg2, bg2, W0, W1, W2);

    // main (4 launches)
    // layer0 GEMM: x @ W0 -> H0
    gemm_mma_kernel<<<(N_NODES + 127) / 128, 256, SMEM_G>>>(x, Wh, Wl, H);
    // layer0 gather + b0 + act, then layer1 GEMM (W1) -> H1
    fused_gg_kernel<<<(N_NODES + 255) / 256, 512, SMEM_F>>>(H, Wh + 8192, Wl + 8192, b0, A);
    // layer1 gather + b1 + act, then layer2 GEMM (W2) -> H2
    fused_gg_kernel<<<(N_NODES + 255) / 256, 512, SMEM_F>>>(A, Wh + 16384, Wl + 16384, b1, H);
    // layer2 gather + b2 + final act -> out
    gather_final_kernel<<<(N_NODES * 32 + 255) / 256, 256>>>(H, b2, out);
}